// round 13
// baseline (speedup 1.0000x reference)
#include <cuda_runtime.h>

#define N_BATCH 4
#define C_CH    256
#define C2      (C_CH / 2)        // 128 float2 lanes
#define H_DIM   96
#define W_DIM   96
#define HW      (H_DIM * W_DIM)
#define OUTS    7
#define BINS    (OUTS * OUTS)     // 49
#define G_SAMP  (OUTS * 2)
#define SPATIAL_SCALE 0.0625f
#define TPB     128               // thread = 2 channels, block = 1 roi

#define SSTR    17                // stage stride (odd -> 2-way STS max)
#define NB_A    17
#define NB_B    16
#define NB_C    16

// Scratch: NHWC-transposed features (b, h, w, c)
__device__ float g_featT[(size_t)N_BATCH * HW * C_CH];

// ---------------------------------------------------------------------------
// Transpose (N, C, HW) -> (N, HW, C), 32x32 smem tile.
// ---------------------------------------------------------------------------
__global__ void nchw_to_nhwc(const float* __restrict__ in) {
    __shared__ float tile[32][33];
    const int n   = blockIdx.z;
    const int hw0 = blockIdx.x * 32;
    const int c0  = blockIdx.y * 32;
    const float* inp = in + (size_t)n * C_CH * HW;
    float* op = g_featT + (size_t)n * HW * C_CH;

    const int x = hw0 + threadIdx.x;
#pragma unroll
    for (int j = 0; j < 32; j += 8) {
        const int cc = c0 + threadIdx.y + j;
        tile[threadIdx.y + j][threadIdx.x] = inp[(size_t)cc * HW + x];
    }
    __syncthreads();
    const int cx = c0 + threadIdx.x;
#pragma unroll
    for (int j = 0; j < 32; j += 8) {
        const int hh = hw0 + threadIdx.y + j;
        op[(size_t)hh * C_CH + cx] = tile[threadIdx.x][threadIdx.y + j];
    }
}

// ---------------------------------------------------------------------------
// RoI Align: block = 1 roi, 128 threads, thread = 2 channels.
// Per-bin separable corner dedup: the 4x4 corner cross-product collapses to
// ny*nx unique texels (weights summed, 0.25 sample-mean folded 0.5/axis,
// zero-weight entries dropped). Counts are block-uniform -> uniform guards.
// ---------------------------------------------------------------------------
__global__ __launch_bounds__(TPB, 8) void roi_align_kernel(
    const float* __restrict__ rois,
    float* __restrict__ out)
{
    __shared__ int   s_ylo[G_SAMP], s_yhi[G_SAMP];   // (b*H+y)*W*C2
    __shared__ float s_wyl[G_SAMP], s_wyh[G_SAMP];
    __shared__ int   s_xlo[G_SAMP], s_xhi[G_SAMP];   // x*C2
    __shared__ float s_wxl[G_SAMP], s_wxh[G_SAMP];
    __shared__ int4   s_yoff[BINS];                  // unique y offsets (padded 0)
    __shared__ float4 s_ywt[BINS];                   // summed y weights * 0.5
    __shared__ int4   s_xoff[BINS];
    __shared__ float4 s_xwt[BINS];
    __shared__ int    s_cnt[BINS];                   // ny | nx<<8
    __shared__ float  stage[C_CH * SSTR];            // 17408 B

    const int k   = blockIdx.x;
    const int tid = threadIdx.x;

    // ---- 1D interpolation tables (28 threads) ----
    if (tid < 2 * G_SAMP) {
        const int axis = tid / G_SAMP;   // 0 = y, 1 = x
        const int g    = tid % G_SAMP;
        const float* r = rois + (size_t)k * 5;
        const int   b  = (int)r[0];
        const float x1 = r[1] * SPATIAL_SCALE;
        const float y1 = r[2] * SPATIAL_SCALE;
        const float x2 = r[3] * SPATIAL_SCALE;
        const float y2 = r[4] * SPATIAL_SCALE;

        float start, binsz;
        if (axis == 0) { start = y1; binsz = fmaxf(y2 - y1, 1.0f) * (1.0f / OUTS); }
        else           { start = x1; binsz = fmaxf(x2 - x1, 1.0f) * (1.0f / OUTS); }

        const float off   = (float)(g >> 1) + 0.25f + 0.5f * (float)(g & 1);
        const float coord = fmaf(binsz, off, start);
        const bool  valid = (coord >= -1.0f) && (coord <= 96.0f);
        const float cc    = fminf(fmaxf(coord, 0.0f), 95.0f);
        const float lof   = floorf(cc);
        const int   lo    = (int)lof;
        const int   hi    = min(lo + 1, 95);
        const float fr    = cc - lof;
        const float wl    = valid ? 1.0f - fr : 0.0f;
        const float wh    = valid ? fr        : 0.0f;

        if (axis == 0) {
            s_ylo[g] = (b * H_DIM + lo) * W_DIM * C2;
            s_yhi[g] = (b * H_DIM + hi) * W_DIM * C2;
            s_wyl[g] = wl; s_wyh[g] = wh;
        } else {
            s_xlo[g] = lo * C2;
            s_xhi[g] = hi * C2;
            s_wxl[g] = wl; s_wxh[g] = wh;
        }
    }
    __syncthreads();

    // ---- Per-bin separable corner dedup (49 threads, one per bin) ----
    if (tid < BINS) {
        const int i = tid / OUTS;
        const int j = tid - i * OUTS;
        const int gy0 = 2 * i, gy1 = 2 * i + 1;
        const int gx0 = 2 * j, gx1 = 2 * j + 1;

        int   co[4]; float cw[4];
        int*   uo;   float* uw;
        int n;

        // --- y axis ---
        co[0] = s_ylo[gy0]; cw[0] = 0.5f * s_wyl[gy0];
        co[1] = s_yhi[gy0]; cw[1] = 0.5f * s_wyh[gy0];
        co[2] = s_ylo[gy1]; cw[2] = 0.5f * s_wyl[gy1];
        co[3] = s_yhi[gy1]; cw[3] = 0.5f * s_wyh[gy1];
        uo = (int*)&s_yoff[tid]; uw = (float*)&s_ywt[tid];
        uo[0] = uo[1] = uo[2] = uo[3] = 0;
        uw[0] = uw[1] = uw[2] = uw[3] = 0.0f;
        n = 0;
#pragma unroll
        for (int e = 0; e < 4; e++) {
            if (cw[e] == 0.0f) continue;
            bool found = false;
            for (int q = 0; q < n; q++)
                if (uo[q] == co[e]) { uw[q] += cw[e]; found = true; break; }
            if (!found) { uo[n] = co[e]; uw[n] = cw[e]; n++; }
        }
        const int ny = n;

        // --- x axis ---
        co[0] = s_xlo[gx0]; cw[0] = 0.5f * s_wxl[gx0];
        co[1] = s_xhi[gx0]; cw[1] = 0.5f * s_wxh[gx0];
        co[2] = s_xlo[gx1]; cw[2] = 0.5f * s_wxl[gx1];
        co[3] = s_xhi[gx1]; cw[3] = 0.5f * s_wxh[gx1];
        uo = (int*)&s_xoff[tid]; uw = (float*)&s_xwt[tid];
        uo[0] = uo[1] = uo[2] = uo[3] = 0;
        uw[0] = uw[1] = uw[2] = uw[3] = 0.0f;
        n = 0;
#pragma unroll
        for (int e = 0; e < 4; e++) {
            if (cw[e] == 0.0f) continue;
            bool found = false;
            for (int q = 0; q < n; q++)
                if (uo[q] == co[e]) { uw[q] += cw[e]; found = true; break; }
            if (!found) { uo[n] = co[e]; uw[n] = cw[e]; n++; }
        }
        s_cnt[tid] = ny | (n << 8);
    }
    __syncthreads();

    const float2* fp = (const float2*)g_featT + tid;   // 2 channels per thread
    const int c0 = 2 * tid;
    float* obase = out + (size_t)k * C_CH * BINS;

#define XTERM(YO, WY, XOE, XWE, QX)                                           \
    if ((QX) < nx) {                                                          \
        const float2 v = __ldg(fp + (YO) + (XOE));                            \
        const float  w = (WY) * (XWE);                                        \
        ax += w * v.x; ay += w * v.y;                                         \
    }

#define YROW(YOE, YWE, QY)                                                    \
    if ((QY) < ny) {                                                          \
        const int   yo_ = (YOE);                                              \
        const float wy_ = (YWE);                                              \
        XTERM(yo_, wy_, xo.x, xw.x, 0)                                        \
        XTERM(yo_, wy_, xo.y, xw.y, 1)                                        \
        XTERM(yo_, wy_, xo.z, xw.z, 2)                                        \
        XTERM(yo_, wy_, xo.w, xw.w, 3)                                        \
    }

#define DO_PHASE(B0, NB)                                                      \
    {                                                                         \
        for (int b = (B0); b < (B0) + (NB); b++) {                            \
            const int4   yo = s_yoff[b];                                      \
            const float4 yw = s_ywt[b];                                       \
            const int4   xo = s_xoff[b];                                      \
            const float4 xw = s_xwt[b];                                       \
            const int cnt = s_cnt[b];                                         \
            const int ny = cnt & 0xFF, nx = cnt >> 8;                         \
            float ax = 0.f, ay = 0.f;                                         \
            YROW(yo.x, yw.x, 0)                                               \
            YROW(yo.y, yw.y, 1)                                               \
            YROW(yo.z, yw.z, 2)                                               \
            YROW(yo.w, yw.w, 3)                                               \
            stage[(c0    ) * SSTR + (b - (B0))] = ax;                         \
            stage[(c0 + 1) * SSTR + (b - (B0))] = ay;                         \
        }                                                                     \
        __syncthreads();                                                      \
        for (int t = tid; t < C_CH * (NB); t += TPB) {                        \
            const int c  = t / (NB);                                          \
            const int lb = t - c * (NB);                                      \
            obase[c * BINS + (B0) + lb] = stage[c * SSTR + lb];               \
        }                                                                     \
        __syncthreads();                                                      \
    }

    DO_PHASE(0, NB_A)
    DO_PHASE(NB_A, NB_B)
    DO_PHASE(NB_A + NB_B, NB_C)
#undef DO_PHASE
#undef YROW
#undef XTERM
}

extern "C" void kernel_launch(void* const* d_in, const int* in_sizes, int n_in,
                              void* d_out, int out_size) {
    const float* features = (const float*)d_in[0];
    const float* rois     = (const float*)d_in[1];
    float* out            = (float*)d_out;
    const int K = in_sizes[1] / 5;

    // 1) NCHW -> NHWC transpose into scratch
    nchw_to_nhwc<<<dim3(HW / 32, C_CH / 32, N_BATCH), dim3(32, 8)>>>(features);

    // 2) RoI Align gather with per-bin deduplicated corner lists
    roi_align_kernel<<<K, TPB>>>(rois, out);
}